// round 6
// baseline (speedup 1.0000x reference)
#include <cuda_runtime.h>
#include <cstdint>

// Problem constants
#define B_  4
#define L_  2048
#define D_  1024
#define H_  16
#define HD_ 64
#define NT_ (B_ * L_)          // 8192 tokens
#define BH_ (B_ * H_)          // 64 head-streams

// Pre-split scratch ({hi,lo} float2 per element) + plain Q.
__device__ float2 g_x_split[(size_t)NT_ * D_];          // 67 MB
__device__ float2 g_wqkv_split[(size_t)3 * D_ * D_];    // 25 MB
__device__ float2 g_wout_split[(size_t)D_ * D_];        // 8.4 MB
__device__ float  g_q[(size_t)BH_ * L_ * HD_];          // 33.5 MB
__device__ float2 g_k_split[(size_t)BH_ * L_ * HD_];    // 67 MB  [bh][l][d]
__device__ float2 g_vt_split[(size_t)BH_ * HD_ * L_];   // 67 MB  [bh][d][l]
__device__ float2 g_ctx_split[(size_t)NT_ * D_];        // 67 MB

__device__ __forceinline__ uint32_t smem_u32(const void* p) {
    uint32_t a;
    asm("{ .reg .u64 t; cvta.to.shared.u64 t, %1; cvt.u32.u64 %0, t; }"
        : "=r"(a) : "l"(p));
    return a;
}
__device__ __forceinline__ void cp_async16(uint32_t saddr, const void* gaddr) {
    asm volatile("cp.async.cg.shared.global [%0], [%1], 16;"
                 :: "r"(saddr), "l"(gaddr) : "memory");
}
__device__ __forceinline__ void cp_commit() {
    asm volatile("cp.async.commit_group;" ::: "memory");
}
__device__ __forceinline__ void cp_wait2() {
    asm volatile("cp.async.wait_group 2;" ::: "memory");
}
__device__ __forceinline__ void cp_wait0() {
    asm volatile("cp.async.wait_group 0;" ::: "memory");
}

__device__ __forceinline__ void mma_tf32(float& c0, float& c1, float& c2, float& c3,
                                         uint32_t a0, uint32_t a1, uint32_t a2, uint32_t a3,
                                         uint32_t b0, uint32_t b1) {
    asm volatile(
        "mma.sync.aligned.m16n8k8.row.col.f32.tf32.tf32.f32 "
        "{%0,%1,%2,%3}, {%4,%5,%6,%7}, {%8,%9}, {%0,%1,%2,%3};"
        : "+f"(c0), "+f"(c1), "+f"(c2), "+f"(c3)
        : "r"(a0), "r"(a1), "r"(a2), "r"(a3), "r"(b0), "r"(b1));
}

__device__ __forceinline__ void split_tf32_f(float f, uint32_t& hi, uint32_t& lo) {
    uint32_t h;
    asm("cvt.rna.tf32.f32 %0, %1;" : "=r"(h) : "f"(f));
    hi = h;
    lo = __float_as_uint(f - __uint_as_float(h));
}
__device__ __forceinline__ float2 split_pair(float f) {
    uint32_t h, l;
    split_tf32_f(f, h, l);
    return make_float2(__uint_as_float(h), __uint_as_float(l));
}

// ---------------------------------------------------------------------------
// Split prep: in (fp32) -> out ({hi,lo} float2), vectorized by 4.
// ---------------------------------------------------------------------------
__global__ void split_kernel(const float4* __restrict__ in,
                             float4* __restrict__ out, int n4)
{
    int i = blockIdx.x * blockDim.x + threadIdx.x;
    if (i >= n4) return;
    float4 v = in[i];
    float2 s0 = split_pair(v.x), s1 = split_pair(v.y);
    float2 s2 = split_pair(v.z), s3 = split_pair(v.w);
    out[2 * i + 0] = make_float4(s0.x, s0.y, s1.x, s1.y);
    out[2 * i + 1] = make_float4(s2.x, s2.y, s3.x, s3.y);
}

// ---------------------------------------------------------------------------
// 3xTF32 GEMM on pre-split operands. A2[M][K], B2[N][K] are {hi,lo} float2.
// CTA 128x128, BK=32, 8 warps (2M x 4N), 3-stage cp.async pipeline.
// mode 0: plain fp32 store to C. mode 1: QKV epilogue -> q plain,
//         k split [bh][l][d], v split transposed [bh][d][l].
// ---------------------------------------------------------------------------
#define PAD2 36                               // float2 per row (32 + 4 pad)
#define TILE_F2 (128 * PAD2)                  // 4608 float2 = 36864 B
#define STAGE_F2 (2 * TILE_F2)                // A + B per stage
#define GK_SMEM_BYTES (3 * STAGE_F2 * 8)      // 221184 B

__global__ __launch_bounds__(256) void gemm_tc_kernel(
    const float2* __restrict__ A2, const float2* __restrict__ B2,
    float* __restrict__ C, float* __restrict__ qo,
    float2* __restrict__ ko, float2* __restrict__ vo,
    int M, int N, int K, int mode)
{
    extern __shared__ float2 smem2[];   // [stage][A(128*36) | B(128*36)]

    const int t    = threadIdx.x;
    const int wid  = t >> 5;
    const int lane = t & 31;
    const int g    = lane >> 2;
    const int c4   = lane & 3;
    const int m0   = blockIdx.y * 128;
    const int n0   = blockIdx.x * 128;
    const int wm   = (wid & 1) * 64;
    const int wn   = (wid >> 1) * 32;

    float acc[4][4][4] = {};
    const int nchunks = K >> 5;

    // loader: 2048 16B-chunks per matrix per chunk; 8 per thread each
    auto load_chunk = [&](int c) {
        const int s  = c % 3;
        const int k0 = c * 32;
        const uint32_t sA = smem_u32(smem2 + s * STAGE_F2);
        const uint32_t sB = sA + TILE_F2 * 8;
        #pragma unroll
        for (int u = 0; u < 8; u++) {
            int idx = t + u * 256;
            int row = idx >> 4;
            int grp = idx & 15;
            cp_async16(sA + (row * PAD2 + grp * 2) * 8,
                       A2 + (size_t)(m0 + row) * K + k0 + grp * 2);
            cp_async16(sB + (row * PAD2 + grp * 2) * 8,
                       B2 + (size_t)(n0 + row) * K + k0 + grp * 2);
        }
        cp_commit();
    };

    load_chunk(0);
    load_chunk(1);

    for (int c = 0; c < nchunks; c++) {
        if (c + 2 < nchunks) { load_chunk(c + 2); cp_wait2(); }
        else                 { cp_wait0(); }
        __syncthreads();

        const float2* As = smem2 + (c % 3) * STAGE_F2;
        const float2* Bs = As + TILE_F2;

        #pragma unroll
        for (int kk = 0; kk < 32; kk += 8) {
            uint32_t ah[4][4], al[4][4], bh[4][2], bl[4][2];
            #pragma unroll
            for (int mi = 0; mi < 4; mi++) {
                const float2* base = As + (wm + mi * 16 + g) * PAD2 + kk + c4;
                float2 p0 = base[0];
                float2 p1 = base[8 * PAD2];
                float2 p2 = base[4];
                float2 p3 = base[8 * PAD2 + 4];
                ah[mi][0] = __float_as_uint(p0.x); al[mi][0] = __float_as_uint(p0.y);
                ah[mi][1] = __float_as_uint(p1.x); al[mi][1] = __float_as_uint(p1.y);
                ah[mi][2] = __float_as_uint(p2.x); al[mi][2] = __float_as_uint(p2.y);
                ah[mi][3] = __float_as_uint(p3.x); al[mi][3] = __float_as_uint(p3.y);
            }
            #pragma unroll
            for (int ni = 0; ni < 4; ni++) {
                const float2* base = Bs + (wn + ni * 8 + g) * PAD2 + kk + c4;
                float2 p0 = base[0];
                float2 p1 = base[4];
                bh[ni][0] = __float_as_uint(p0.x); bl[ni][0] = __float_as_uint(p0.y);
                bh[ni][1] = __float_as_uint(p1.x); bl[ni][1] = __float_as_uint(p1.y);
            }
            #pragma unroll
            for (int mi = 0; mi < 4; mi++)
                #pragma unroll
                for (int ni = 0; ni < 4; ni++) {
                    mma_tf32(acc[mi][ni][0], acc[mi][ni][1],
                             acc[mi][ni][2], acc[mi][ni][3],
                             ah[mi][0], ah[mi][1], ah[mi][2], ah[mi][3],
                             bl[ni][0], bl[ni][1]);
                    mma_tf32(acc[mi][ni][0], acc[mi][ni][1],
                             acc[mi][ni][2], acc[mi][ni][3],
                             al[mi][0], al[mi][1], al[mi][2], al[mi][3],
                             bh[ni][0], bh[ni][1]);
                    mma_tf32(acc[mi][ni][0], acc[mi][ni][1],
                             acc[mi][ni][2], acc[mi][ni][3],
                             ah[mi][0], ah[mi][1], ah[mi][2], ah[mi][3],
                             bh[ni][0], bh[ni][1]);
                }
        }
        __syncthreads();
    }

    // ---- epilogue ----
    #pragma unroll
    for (int mi = 0; mi < 4; mi++) {
        #pragma unroll
        for (int half = 0; half < 2; half++) {
            const int m = m0 + wm + mi * 16 + g + half * 8;
            if (mode == 0) {
                #pragma unroll
                for (int ni = 0; ni < 4; ni++) {
                    int n = n0 + wn + ni * 8 + c4 * 2;
                    float2 v = half == 0
                        ? make_float2(acc[mi][ni][0], acc[mi][ni][1])
                        : make_float2(acc[mi][ni][2], acc[mi][ni][3]);
                    *(float2*)(C + (size_t)m * N + n) = v;
                }
            } else {
                const int b = m >> 11;
                const int l = m & 2047;
                #pragma unroll
                for (int ni = 0; ni < 4; ni++) {
                    int n     = n0 + wn + ni * 8 + c4 * 2;
                    int which = n >> 10;
                    int rem   = n & 1023;
                    int h     = rem >> 6;
                    int d     = rem & 63;
                    int bh_i  = b * H_ + h;
                    float v0 = half == 0 ? acc[mi][ni][0] : acc[mi][ni][2];
                    float v1 = half == 0 ? acc[mi][ni][1] : acc[mi][ni][3];
                    if (which == 0) {
                        size_t idx = ((size_t)bh_i * L_ + l) * HD_ + d;
                        *(float2*)(qo + idx) = make_float2(v0, v1);
                    } else if (which == 1) {
                        size_t idx = ((size_t)bh_i * L_ + l) * HD_ + d;
                        float2 s0 = split_pair(v0);
                        float2 s1 = split_pair(v1);
                        *(float4*)(ko + idx) = make_float4(s0.x, s0.y, s1.x, s1.y);
                    } else {
                        size_t idx = ((size_t)bh_i * HD_ + d) * L_ + l;
                        vo[idx]      = split_pair(v0);
                        vo[idx + L_] = split_pair(v1);
                    }
                }
            }
        }
    }
}

// ---------------------------------------------------------------------------
// Tensor-core flash attention, causal, 3xTF32.
// Q plain (split on the fly, cheap), K/V pre-split {hi,lo} from gemm epilogue,
// V pre-transposed in gmem. 4 warps, 64-query tile.
// ---------------------------------------------------------------------------
#define APAD 68    // plain-float rows: pad to 68 floats
                   // split rows: 68 float2 = 136 floats (stride ≡ 8 mod 64)
#define ATT_SMEM_BYTES ((64 * APAD * 4) * 2 + (64 * APAD * 8) * 2)  // 104448 B

__global__ __launch_bounds__(128) void attn_tc_kernel(
    const float* __restrict__ q, const float2* __restrict__ ksp,
    const float2* __restrict__ vtsp, float2* __restrict__ ctx)
{
    const int qt = blockIdx.x;
    const int bh = blockIdx.y;

    extern __shared__ float sm[];
    float*  Qs   = sm;                          // [q][d] plain, pad 68
    float2* Ks2  = (float2*)(sm + 64 * APAD);   // [k][d] split, pad 68 f2
    float2* Vts2 = Ks2 + 64 * APAD;             // [d][k] split, pad 68 f2
    float*  Ss   = (float*)(Vts2 + 64 * APAD);  // [q][k] plain, pad 68

    const int t    = threadIdx.x;
    const int w    = t >> 5;
    const int lane = t & 31;
    const int g    = lane >> 2;
    const int c4   = lane & 3;
    const int q0   = w * 16;

    const float*  Qg = q    + ((size_t)bh * L_ + (size_t)qt * 64) * HD_;
    const float2* Kg = ksp  + ((size_t)bh * L_) * HD_;
    const float2* Vt = vtsp + ((size_t)bh * HD_) * L_;

    // Load Q tile [64][64] plain
    #pragma unroll
    for (int u = 0; u < 8; u++) {
        int idx = t + u * 128;
        int row = idx >> 4;
        int cg  = idx & 15;
        float4 v = *(const float4*)(Qg + (size_t)row * HD_ + cg * 4);
        *(float4*)&Qs[row * APAD + cg * 4] = v;
    }

    float m0r = -1.0e30f, m1r = -1.0e30f;
    float l0r = 0.0f,     l1r = 0.0f;
    float oacc[8][4] = {};

    const uint32_t ksa = smem_u32(Ks2);
    const uint32_t vsa = smem_u32(Vts2);

    for (int kt = 0; kt <= qt; kt++) {
        __syncthreads();

        // K tile: 64 rows x 64 f2 = 2048 16B chunks; V tile same (pre-transposed)
        #pragma unroll
        for (int u = 0; u < 16; u++) {
            int idx = t + u * 128;
            int row = idx >> 5;
            int grp = idx & 31;
            cp_async16(ksa + (row * APAD + grp * 2) * 8,
                       Kg + ((size_t)(kt * 64 + row)) * HD_ + grp * 2);
            cp_async16(vsa + (row * APAD + grp * 2) * 8,
                       Vt + (size_t)row * L_ + kt * 64 + grp * 2);
        }
        cp_commit();
        cp_wait0();
        __syncthreads();

        // ---- S = Q K^T ----
        float sacc[8][4] = {};
        #pragma unroll
        for (int kk = 0; kk < 64; kk += 8) {
            uint32_t ah[4], al[4];
            {
                const float* base = Qs + (q0 + g) * APAD + kk + c4;
                split_tf32_f(base[0],            ah[0], al[0]);
                split_tf32_f(base[8 * APAD],     ah[1], al[1]);
                split_tf32_f(base[4],            ah[2], al[2]);
                split_tf32_f(base[8 * APAD + 4], ah[3], al[3]);
            }
            #pragma unroll
            for (int ni = 0; ni < 8; ni++) {
                const float2* base = Ks2 + (ni * 8 + g) * APAD + kk + c4;
                float2 p0 = base[0];
                float2 p1 = base[4];
                uint32_t bh0 = __float_as_uint(p0.x), bl0 = __float_as_uint(p0.y);
                uint32_t bh1 = __float_as_uint(p1.x), bl1 = __float_as_uint(p1.y);
                mma_tf32(sacc[ni][0], sacc[ni][1], sacc[ni][2], sacc[ni][3],
                         ah[0], ah[1], ah[2], ah[3], bl0, bl1);
                mma_tf32(sacc[ni][0], sacc[ni][1], sacc[ni][2], sacc[ni][3],
                         al[0], al[1], al[2], al[3], bh0, bh1);
                mma_tf32(sacc[ni][0], sacc[ni][1], sacc[ni][2], sacc[ni][3],
                         ah[0], ah[1], ah[2], ah[3], bh0, bh1);
            }
        }

        // ---- scale + causal mask ----
        const int qrow0 = qt * 64 + q0 + g;
        const int qrow1 = qrow0 + 8;
        #pragma unroll
        for (int ni = 0; ni < 8; ni++) {
            int col0 = kt * 64 + ni * 8 + c4 * 2;
            int col1 = col0 + 1;
            sacc[ni][0] = (col0 <= qrow0) ? sacc[ni][0] * 0.125f : -1.0e30f;
            sacc[ni][1] = (col1 <= qrow0) ? sacc[ni][1] * 0.125f : -1.0e30f;
            sacc[ni][2] = (col0 <= qrow1) ? sacc[ni][2] * 0.125f : -1.0e30f;
            sacc[ni][3] = (col1 <= qrow1) ? sacc[ni][3] * 0.125f : -1.0e30f;
        }

        // ---- online softmax ----
        float mx0 = -1.0e30f, mx1 = -1.0e30f;
        #pragma unroll
        for (int ni = 0; ni < 8; ni++) {
            mx0 = fmaxf(mx0, fmaxf(sacc[ni][0], sacc[ni][1]));
            mx1 = fmaxf(mx1, fmaxf(sacc[ni][2], sacc[ni][3]));
        }
        mx0 = fmaxf(mx0, __shfl_xor_sync(0xffffffffu, mx0, 1));
        mx0 = fmaxf(mx0, __shfl_xor_sync(0xffffffffu, mx0, 2));
        mx1 = fmaxf(mx1, __shfl_xor_sync(0xffffffffu, mx1, 1));
        mx1 = fmaxf(mx1, __shfl_xor_sync(0xffffffffu, mx1, 2));

        float mn0 = fmaxf(m0r, mx0);
        float mn1 = fmaxf(m1r, mx1);
        float corr0 = __expf(m0r - mn0);
        float corr1 = __expf(m1r - mn1);
        m0r = mn0; m1r = mn1;

        float sum0 = 0.0f, sum1 = 0.0f;
        #pragma unroll
        for (int ni = 0; ni < 8; ni++) {
            sacc[ni][0] = __expf(sacc[ni][0] - mn0); sum0 += sacc[ni][0];
            sacc[ni][1] = __expf(sacc[ni][1] - mn0); sum0 += sacc[ni][1];
            sacc[ni][2] = __expf(sacc[ni][2] - mn1); sum1 += sacc[ni][2];
            sacc[ni][3] = __expf(sacc[ni][3] - mn1); sum1 += sacc[ni][3];
        }
        sum0 += __shfl_xor_sync(0xffffffffu, sum0, 1);
        sum0 += __shfl_xor_sync(0xffffffffu, sum0, 2);
        sum1 += __shfl_xor_sync(0xffffffffu, sum1, 1);
        sum1 += __shfl_xor_sync(0xffffffffu, sum1, 2);
        l0r = l0r * corr0 + sum0;
        l1r = l1r * corr1 + sum1;

        #pragma unroll
        for (int ni = 0; ni < 8; ni++) {
            oacc[ni][0] *= corr0; oacc[ni][1] *= corr0;
            oacc[ni][2] *= corr1; oacc[ni][3] *= corr1;
        }

        // ---- stage P ----
        #pragma unroll
        for (int ni = 0; ni < 8; ni++) {
            *(float2*)&Ss[(q0 + g    ) * APAD + ni * 8 + c4 * 2] =
                make_float2(sacc[ni][0], sacc[ni][1]);
            *(float2*)&Ss[(q0 + g + 8) * APAD + ni * 8 + c4 * 2] =
                make_float2(sacc[ni][2], sacc[ni][3]);
        }
        __syncwarp();

        // ---- O += P V ----
        #pragma unroll
        for (int kk = 0; kk < 64; kk += 8) {
            uint32_t ah[4], al[4];
            {
                const float* base = Ss + (q0 + g) * APAD + kk + c4;
                split_tf32_f(base[0],            ah[0], al[0]);
                split_tf32_f(base[8 * APAD],     ah[1], al[1]);
                split_tf32_f(base[4],            ah[2], al[2]);
                split_tf32_f(base[8 * APAD + 4], ah[3], al[3]);
            }
            #pragma unroll
            for (int ni = 0; ni < 8; ni++) {
                const float2* base = Vts2 + (ni * 8 + g) * APAD + kk + c4;
                float2 p0 = base[0];
                float2 p1 = base[4];
                uint32_t bh0 = __float_as_uint(p0.x), bl0 = __float_as_uint(p0.y);
                uint32_t bh1 = __float_as_uint(p1.x), bl1 = __float_as_uint(p1.y);
                mma_tf32(oacc[ni][0], oacc[ni][1], oacc[ni][2], oacc[ni][3],
                         ah[0], ah[1], ah[2], ah[3], bl0, bl1);
                mma_tf32(oacc[ni][0], oacc[ni][1], oacc[ni][2], oacc[ni][3],
                         al[0], al[1], al[2], al[3], bh0, bh1);
                mma_tf32(oacc[ni][0], oacc[ni][1], oacc[ni][2], oacc[ni][3],
                         ah[0], ah[1], ah[2], ah[3], bh0, bh1);
            }
        }
    }

    // ---- normalize + write ctx_split [B][L][H*HD] as {hi,lo} ----
    const int b = bh >> 4;
    const int h = bh & 15;
    const float inv0 = 1.0f / l0r;
    const float inv1 = 1.0f / l1r;
    const int l0i = qt * 64 + q0 + g;
    const int l1i = l0i + 8;
    #pragma unroll
    for (int ni = 0; ni < 8; ni++) {
        int d = ni * 8 + c4 * 2;
        size_t i0 = (((size_t)b * L_ + l0i) * H_ + h) * HD_ + d;
        size_t i1 = (((size_t)b * L_ + l1i) * H_ + h) * HD_ + d;
        float2 s00 = split_pair(oacc[ni][0] * inv0);
        float2 s01 = split_pair(oacc[ni][1] * inv0);
        float2 s10 = split_pair(oacc[ni][2] * inv1);
        float2 s11 = split_pair(oacc[ni][3] * inv1);
        *(float4*)(ctx + i0) = make_float4(s00.x, s00.y, s01.x, s01.y);
        *(float4*)(ctx + i1) = make_float4(s10.x, s10.y, s11.x, s11.y);
    }
}

// ---------------------------------------------------------------------------
extern "C" void kernel_launch(void* const* d_in, const int* in_sizes, int n_in,
                              void* d_out, int out_size)
{
    const float* x     = (const float*)d_in[0];
    const float* W_qkv = (const float*)d_in[1];
    const float* W_out = (const float*)d_in[2];
    float* out = (float*)d_out;

    float2 *xs, *wqs, *wos, *ks, *vts, *cs;
    float *qp;
    cudaGetSymbolAddress((void**)&xs,  g_x_split);
    cudaGetSymbolAddress((void**)&wqs, g_wqkv_split);
    cudaGetSymbolAddress((void**)&wos, g_wout_split);
    cudaGetSymbolAddress((void**)&qp,  g_q);
    cudaGetSymbolAddress((void**)&ks,  g_k_split);
    cudaGetSymbolAddress((void**)&vts, g_vt_split);
    cudaGetSymbolAddress((void**)&cs,  g_ctx_split);

    cudaFuncSetAttribute(gemm_tc_kernel,
                         cudaFuncAttributeMaxDynamicSharedMemorySize, GK_SMEM_BYTES);
    cudaFuncSetAttribute(attn_tc_kernel,
                         cudaFuncAttributeMaxDynamicSharedMemorySize, ATT_SMEM_BYTES);

    // 0) pre-split inputs
    split_kernel<<<(NT_ * D_ / 4 + 255) / 256, 256>>>(
        (const float4*)x, (float4*)xs, NT_ * D_ / 4);
    split_kernel<<<(3 * D_ * D_ / 4 + 255) / 256, 256>>>(
        (const float4*)W_qkv, (float4*)wqs, 3 * D_ * D_ / 4);
    split_kernel<<<(D_ * D_ / 4 + 255) / 256, 256>>>(
        (const float4*)W_out, (float4*)wos, D_ * D_ / 4);

    // 1) QKV projection; epilogue emits q plain, k split, v split-transposed
    gemm_tc_kernel<<<dim3(3 * D_ / 128, NT_ / 128), 256, GK_SMEM_BYTES>>>(
        xs, wqs, nullptr, qp, ks, vts, NT_, 3 * D_, D_, 1);

    // 2) causal flash attention -> ctx split
    attn_tc_kernel<<<dim3(L_ / 64, BH_), 128, ATT_SMEM_BYTES>>>(qp, ks, vts, cs);

    // 3) output projection -> plain fp32 result
    gemm_tc_kernel<<<dim3(D_ / 128, NT_ / 128), 256, GK_SMEM_BYTES>>>(
        cs, wos, out, nullptr, nullptr, nullptr, NT_, D_, D_, 0);
}

// round 7
// speedup vs baseline: 1.2400x; 1.2400x over previous
#include <cuda_runtime.h>
#include <cstdint>

// Problem constants
#define B_  4
#define L_  2048
#define D_  1024
#define H_  16
#define HD_ 64
#define NT_ (B_ * L_)          // 8192 tokens
#define BH_ (B_ * H_)          // 64 head-streams

// Scratch: q/k in [bh][l][d], v transposed [bh][d][l], ctx in [B,L,D].
__device__ float g_q[(size_t)BH_ * L_ * HD_];
__device__ float g_k[(size_t)BH_ * L_ * HD_];
__device__ float g_vt[(size_t)BH_ * HD_ * L_];
__device__ float g_ctx[(size_t)NT_ * D_];

__device__ __forceinline__ uint32_t smem_u32(const void* p) {
    uint32_t a;
    asm("{ .reg .u64 t; cvta.to.shared.u64 t, %1; cvt.u32.u64 %0, t; }"
        : "=r"(a) : "l"(p));
    return a;
}
__device__ __forceinline__ void cp_async16(uint32_t saddr, const void* gaddr) {
    asm volatile("cp.async.cg.shared.global [%0], [%1], 16;"
                 :: "r"(saddr), "l"(gaddr) : "memory");
}
__device__ __forceinline__ void cp_commit() {
    asm volatile("cp.async.commit_group;" ::: "memory");
}
__device__ __forceinline__ void cp_wait1() {
    asm volatile("cp.async.wait_group 1;" ::: "memory");
}
__device__ __forceinline__ void cp_wait0() {
    asm volatile("cp.async.wait_group 0;" ::: "memory");
}

__device__ __forceinline__ void mma_tf32(float& c0, float& c1, float& c2, float& c3,
                                         uint32_t a0, uint32_t a1, uint32_t a2, uint32_t a3,
                                         uint32_t b0, uint32_t b1) {
    asm volatile(
        "mma.sync.aligned.m16n8k8.row.col.f32.tf32.tf32.f32 "
        "{%0,%1,%2,%3}, {%4,%5,%6,%7}, {%8,%9}, {%0,%1,%2,%3};"
        : "+f"(c0), "+f"(c1), "+f"(c2), "+f"(c3)
        : "r"(a0), "r"(a1), "r"(a2), "r"(a3), "r"(b0), "r"(b1));
}

__device__ __forceinline__ void split_tf32(uint32_t x, uint32_t& hi, uint32_t& lo) {
    float f = __uint_as_float(x);
    uint32_t h;
    asm("cvt.rna.tf32.f32 %0, %1;" : "=r"(h) : "f"(f));
    hi = h;
    lo = __float_as_uint(f - __uint_as_float(h));
}

// ---------------------------------------------------------------------------
// 3xTF32 split-precision GEMM via mma.sync (R5 structure, occupancy 2).
// CTA 128x128, BK=32, 8 warps (2M x 4N), double-buffered cp.async.
// mode 0: plain store; mode 1: QKV scatter -> q/k [bh][l][d], v^T [bh][d][l].
// ---------------------------------------------------------------------------
#define PAD_ 36
#define TILE_FLOATS (128 * PAD_)
#define STAGE_FLOATS (2 * TILE_FLOATS)
#define GK_SMEM_BYTES (2 * STAGE_FLOATS * 4)     // 73728 B (2 CTAs/SM fit)

__global__ __launch_bounds__(256, 2) void gemm_tc_kernel(
    const float* __restrict__ A, const float* __restrict__ Bm,
    float* __restrict__ C, float* __restrict__ qo,
    float* __restrict__ ko, float* __restrict__ vo,
    int M, int N, int K, int mode)
{
    extern __shared__ float smem[];

    const int t    = threadIdx.x;
    const int wid  = t >> 5;
    const int lane = t & 31;
    const int g    = lane >> 2;
    const int c4   = lane & 3;
    const int m0   = blockIdx.y * 128;
    const int n0   = blockIdx.x * 128;
    const int wm   = (wid & 1) * 64;
    const int wn   = (wid >> 1) * 32;

    float acc[4][4][4] = {};
    const int nchunks = K >> 5;

    {
        const uint32_t sA = smem_u32(smem);
        const uint32_t sB = sA + TILE_FLOATS * 4;
        #pragma unroll
        for (int u = 0; u < 4; u++) {
            int idx = t + u * 256;
            int row = idx >> 3;
            int grp = idx & 7;
            cp_async16(sA + (row * PAD_ + grp * 4) * 4,
                       A  + (size_t)(m0 + row) * K + grp * 4);
            cp_async16(sB + (row * PAD_ + grp * 4) * 4,
                       Bm + (size_t)(n0 + row) * K + grp * 4);
        }
        cp_commit();
    }

    for (int c = 0; c < nchunks; c++) {
        if (c + 1 < nchunks) {
            const int s = (c + 1) & 1;
            const int k0 = (c + 1) * 32;
            const uint32_t sA = smem_u32(smem + s * STAGE_FLOATS);
            const uint32_t sB = sA + TILE_FLOATS * 4;
            #pragma unroll
            for (int u = 0; u < 4; u++) {
                int idx = t + u * 256;
                int row = idx >> 3;
                int grp = idx & 7;
                cp_async16(sA + (row * PAD_ + grp * 4) * 4,
                           A  + (size_t)(m0 + row) * K + k0 + grp * 4);
                cp_async16(sB + (row * PAD_ + grp * 4) * 4,
                           Bm + (size_t)(n0 + row) * K + k0 + grp * 4);
            }
            cp_commit();
            cp_wait1();
        } else {
            cp_wait0();
        }
        __syncthreads();

        const float* As = smem + (c & 1) * STAGE_FLOATS;
        const float* Bs = As + TILE_FLOATS;
        const uint32_t* Au = (const uint32_t*)As;
        const uint32_t* Bu = (const uint32_t*)Bs;

        #pragma unroll
        for (int kk = 0; kk < 32; kk += 8) {
            uint32_t ah[4][4], al[4][4], bh[4][2], bl[4][2];
            #pragma unroll
            for (int mi = 0; mi < 4; mi++) {
                const uint32_t* base = Au + (wm + mi * 16 + g) * PAD_ + kk + c4;
                split_tf32(base[0],            ah[mi][0], al[mi][0]);
                split_tf32(base[8 * PAD_],     ah[mi][1], al[mi][1]);
                split_tf32(base[4],            ah[mi][2], al[mi][2]);
                split_tf32(base[8 * PAD_ + 4], ah[mi][3], al[mi][3]);
            }
            #pragma unroll
            for (int ni = 0; ni < 4; ni++) {
                const uint32_t* base = Bu + (wn + ni * 8 + g) * PAD_ + kk + c4;
                split_tf32(base[0], bh[ni][0], bl[ni][0]);
                split_tf32(base[4], bh[ni][1], bl[ni][1]);
            }
            #pragma unroll
            for (int mi = 0; mi < 4; mi++)
                #pragma unroll
                for (int ni = 0; ni < 4; ni++) {
                    mma_tf32(acc[mi][ni][0], acc[mi][ni][1],
                             acc[mi][ni][2], acc[mi][ni][3],
                             ah[mi][0], ah[mi][1], ah[mi][2], ah[mi][3],
                             bl[ni][0], bl[ni][1]);
                    mma_tf32(acc[mi][ni][0], acc[mi][ni][1],
                             acc[mi][ni][2], acc[mi][ni][3],
                             al[mi][0], al[mi][1], al[mi][2], al[mi][3],
                             bh[ni][0], bh[ni][1]);
                    mma_tf32(acc[mi][ni][0], acc[mi][ni][1],
                             acc[mi][ni][2], acc[mi][ni][3],
                             ah[mi][0], ah[mi][1], ah[mi][2], ah[mi][3],
                             bh[ni][0], bh[ni][1]);
                }
        }
        __syncthreads();
    }

    #pragma unroll
    for (int mi = 0; mi < 4; mi++) {
        #pragma unroll
        for (int half = 0; half < 2; half++) {
            const int m = m0 + wm + mi * 16 + g + half * 8;
            if (mode == 0) {
                #pragma unroll
                for (int ni = 0; ni < 4; ni++) {
                    int n = n0 + wn + ni * 8 + c4 * 2;
                    float2 v = half == 0
                        ? make_float2(acc[mi][ni][0], acc[mi][ni][1])
                        : make_float2(acc[mi][ni][2], acc[mi][ni][3]);
                    *(float2*)(C + (size_t)m * N + n) = v;
                }
            } else {
                const int b = m >> 11;
                const int l = m & 2047;
                #pragma unroll
                for (int ni = 0; ni < 4; ni++) {
                    int n     = n0 + wn + ni * 8 + c4 * 2;
                    int which = n >> 10;
                    int rem   = n & 1023;
                    int h     = rem >> 6;
                    int d     = rem & 63;
                    int bh_i  = b * H_ + h;
                    float v0 = half == 0 ? acc[mi][ni][0] : acc[mi][ni][2];
                    float v1 = half == 0 ? acc[mi][ni][1] : acc[mi][ni][3];
                    if (which == 0) {
                        size_t idx = ((size_t)bh_i * L_ + l) * HD_ + d;
                        *(float2*)(qo + idx) = make_float2(v0, v1);
                    } else if (which == 1) {
                        size_t idx = ((size_t)bh_i * L_ + l) * HD_ + d;
                        *(float2*)(ko + idx) = make_float2(v0, v1);
                    } else {
                        size_t idx = ((size_t)bh_i * HD_ + d) * L_ + l;
                        vo[idx]      = v0;
                        vo[idx + L_] = v1;
                    }
                }
            }
        }
    }
}

// ---------------------------------------------------------------------------
// Tensor-core flash attention, causal, 3xTF32 (R5 structure).
// V pre-transposed in gmem [bh][d][L] -> straight row copy into smem.
// ---------------------------------------------------------------------------
#define APAD 68
#define ATT_SMEM_BYTES (4 * 64 * APAD * 4)   // 69632 B

__global__ __launch_bounds__(128) void attn_tc_kernel(
    const float* __restrict__ q, const float* __restrict__ k,
    const float* __restrict__ vt, float* __restrict__ ctx)
{
    const int qt = blockIdx.x;
    const int bh = blockIdx.y;

    extern __shared__ float sm[];
    float* Qs  = sm;                    // [q][d]   pad 68
    float* Ks  = sm + 64 * APAD;        // [k][d]   pad 68
    float* Vts = sm + 2 * 64 * APAD;    // [d][k]   pad 68
    float* Ss  = sm + 3 * 64 * APAD;    // [q][k]   pad 68

    const int t    = threadIdx.x;
    const int w    = t >> 5;
    const int lane = t & 31;
    const int g    = lane >> 2;
    const int c4   = lane & 3;
    const int q0   = w * 16;

    const float* Qg = q  + ((size_t)bh * L_ + (size_t)qt * 64) * HD_;
    const float* Kg = k  + ((size_t)bh * L_) * HD_;
    const float* Vg = vt + ((size_t)bh * HD_) * L_;

    #pragma unroll
    for (int u = 0; u < 8; u++) {
        int idx = t + u * 128;
        int row = idx >> 4;
        int cg  = idx & 15;
        float4 v = *(const float4*)(Qg + (size_t)row * HD_ + cg * 4);
        *(float4*)&Qs[row * APAD + cg * 4] = v;
    }

    float m0r = -1.0e30f, m1r = -1.0e30f;
    float l0r = 0.0f,     l1r = 0.0f;
    float oacc[8][4] = {};

    for (int kt = 0; kt <= qt; kt++) {
        __syncthreads();

        // K tile rows [k][d]; V tile rows [d][k] (already transposed in gmem)
        #pragma unroll
        for (int u = 0; u < 8; u++) {
            int idx = t + u * 128;
            int row = idx >> 4;
            int cg  = idx & 15;
            float4 kv = *(const float4*)(Kg + ((size_t)(kt * 64 + row)) * HD_ + cg * 4);
            *(float4*)&Ks[row * APAD + cg * 4] = kv;
            float4 vv = *(const float4*)(Vg + (size_t)row * L_ + kt * 64 + cg * 4);
            *(float4*)&Vts[row * APAD + cg * 4] = vv;
        }
        __syncthreads();

        // ---- S = Q K^T (3xTF32) ----
        float sacc[8][4] = {};
        const uint32_t* Qu = (const uint32_t*)Qs;
        const uint32_t* Ku = (const uint32_t*)Ks;
        #pragma unroll
        for (int kk = 0; kk < 64; kk += 8) {
            uint32_t ah[4], al[4];
            {
                const uint32_t* base = Qu + (q0 + g) * APAD + kk + c4;
                split_tf32(base[0],            ah[0], al[0]);
                split_tf32(base[8 * APAD],     ah[1], al[1]);
                split_tf32(base[4],            ah[2], al[2]);
                split_tf32(base[8 * APAD + 4], ah[3], al[3]);
            }
            #pragma unroll
            for (int ni = 0; ni < 8; ni++) {
                uint32_t bh0, bl0, bh1, bl1;
                const uint32_t* base = Ku + (ni * 8 + g) * APAD + kk + c4;
                split_tf32(base[0], bh0, bl0);
                split_tf32(base[4], bh1, bl1);
                mma_tf32(sacc[ni][0], sacc[ni][1], sacc[ni][2], sacc[ni][3],
                         ah[0], ah[1], ah[2], ah[3], bl0, bl1);
                mma_tf32(sacc[ni][0], sacc[ni][1], sacc[ni][2], sacc[ni][3],
                         al[0], al[1], al[2], al[3], bh0, bh1);
                mma_tf32(sacc[ni][0], sacc[ni][1], sacc[ni][2], sacc[ni][3],
                         ah[0], ah[1], ah[2], ah[3], bh0, bh1);
            }
        }

        // ---- scale + causal mask ----
        const int qrow0 = qt * 64 + q0 + g;
        const int qrow1 = qrow0 + 8;
        #pragma unroll
        for (int ni = 0; ni < 8; ni++) {
            int col0 = kt * 64 + ni * 8 + c4 * 2;
            int col1 = col0 + 1;
            sacc[ni][0] = (col0 <= qrow0) ? sacc[ni][0] * 0.125f : -1.0e30f;
            sacc[ni][1] = (col1 <= qrow0) ? sacc[ni][1] * 0.125f : -1.0e30f;
            sacc[ni][2] = (col0 <= qrow1) ? sacc[ni][2] * 0.125f : -1.0e30f;
            sacc[ni][3] = (col1 <= qrow1) ? sacc[ni][3] * 0.125f : -1.0e30f;
        }

        // ---- online softmax ----
        float mx0 = -1.0e30f, mx1 = -1.0e30f;
        #pragma unroll
        for (int ni = 0; ni < 8; ni++) {
            mx0 = fmaxf(mx0, fmaxf(sacc[ni][0], sacc[ni][1]));
            mx1 = fmaxf(mx1, fmaxf(sacc[ni][2], sacc[ni][3]));
        }
        mx0 = fmaxf(mx0, __shfl_xor_sync(0xffffffffu, mx0, 1));
        mx0 = fmaxf(mx0, __shfl_xor_sync(0xffffffffu, mx0, 2));
        mx1 = fmaxf(mx1, __shfl_xor_sync(0xffffffffu, mx1, 1));
        mx1 = fmaxf(mx1, __shfl_xor_sync(0xffffffffu, mx1, 2));

        float mn0 = fmaxf(m0r, mx0);
        float mn1 = fmaxf(m1r, mx1);
        float corr0 = __expf(m0r - mn0);
        float corr1 = __expf(m1r - mn1);
        m0r = mn0; m1r = mn1;

        float sum0 = 0.0f, sum1 = 0.0f;
        #pragma unroll
        for (int ni = 0; ni < 8; ni++) {
            sacc[ni][0] = __expf(sacc[ni][0] - mn0); sum0 += sacc[ni][0];
            sacc[ni][1] = __expf(sacc[ni][1] - mn0); sum0 += sacc[ni][1];
            sacc[ni][2] = __expf(sacc[ni][2] - mn1); sum1 += sacc[ni][2];
            sacc[ni][3] = __expf(sacc[ni][3] - mn1); sum1 += sacc[ni][3];
        }
        sum0 += __shfl_xor_sync(0xffffffffu, sum0, 1);
        sum0 += __shfl_xor_sync(0xffffffffu, sum0, 2);
        sum1 += __shfl_xor_sync(0xffffffffu, sum1, 1);
        sum1 += __shfl_xor_sync(0xffffffffu, sum1, 2);
        l0r = l0r * corr0 + sum0;
        l1r = l1r * corr1 + sum1;

        #pragma unroll
        for (int ni = 0; ni < 8; ni++) {
            oacc[ni][0] *= corr0; oacc[ni][1] *= corr0;
            oacc[ni][2] *= corr1; oacc[ni][3] *= corr1;
        }

        // ---- stage P ----
        #pragma unroll
        for (int ni = 0; ni < 8; ni++) {
            *(float2*)&Ss[(q0 + g    ) * APAD + ni * 8 + c4 * 2] =
                make_float2(sacc[ni][0], sacc[ni][1]);
            *(float2*)&Ss[(q0 + g + 8) * APAD + ni * 8 + c4 * 2] =
                make_float2(sacc[ni][2], sacc[ni][3]);
        }
        __syncwarp();

        // ---- O += P V (3xTF32) ----
        const uint32_t* Pu = (const uint32_t*)Ss;
        const uint32_t* Vu = (const uint32_t*)Vts;
        #pragma unroll
        for (int kk = 0; kk < 64; kk += 8) {
            uint32_t ah[4], al[4];
            {
                const uint32_t* base = Pu + (q0 + g) * APAD + kk + c4;
                split_tf32(base[0],            ah[0], al[0]);
                split_tf32(base[8 * APAD],     ah[1], al[1]);
                split_tf32(base[4],            ah[2], al[2]);
                split_tf32(base[8 * APAD + 4], ah[3], al[3]);
            }
            #pragma unroll
            for (int ni = 0; ni < 8; ni++) {
                uint32_t bh0, bl0, bh1, bl1;
                const uint32_t* base = Vu + (ni * 8 + g) * APAD + kk + c4;
                split_tf32(base[0], bh0, bl0);
                split_tf32(base[4], bh1, bl1);
                mma_tf32(oacc[ni][0], oacc[ni][1], oacc[ni][2], oacc[ni][3],
                         ah[0], ah[1], ah[2], ah[3], bl0, bl1);
                mma_tf32(oacc[ni][0], oacc[ni][1], oacc[ni][2], oacc[ni][3],
                         al[0], al[1], al[2], al[3], bh0, bh1);
                mma_tf32(oacc[ni][0], oacc[ni][1], oacc[ni][2], oacc[ni][3],
                         ah[0], ah[1], ah[2], ah[3], bh0, bh1);
            }
        }
    }

    // ---- normalize + write ctx [B][L][H*HD] ----
    const int b = bh >> 4;
    const int h = bh & 15;
    const float inv0 = 1.0f / l0r;
    const float inv1 = 1.0f / l1r;
    const int l0i = qt * 64 + q0 + g;
    const int l1i = l0i + 8;
    #pragma unroll
    for (int ni = 0; ni < 8; ni++) {
        int d = ni * 8 + c4 * 2;
        size_t i0 = (((size_t)b * L_ + l0i) * H_ + h) * HD_ + d;
        size_t i1 = (((size_t)b * L_ + l1i) * H_ + h) * HD_ + d;
        *(float2*)(ctx + i0) = make_float2(oacc[ni][0] * inv0, oacc[ni][1] * inv0);
        *(float2*)(ctx + i1) = make_float2(oacc[ni][2] * inv1, oacc[ni][3] * inv1);
    }
}

// ---------------------------------------------------------------------------
extern "C" void kernel_launch(void* const* d_in, const int* in_sizes, int n_in,
                              void* d_out, int out_size)
{
    const float* x     = (const float*)d_in[0];
    const float* W_qkv = (const float*)d_in[1];
    const float* W_out = (const float*)d_in[2];
    float* out = (float*)d_out;

    float *qp, *kp, *vtp, *ctxp;
    cudaGetSymbolAddress((void**)&qp,   g_q);
    cudaGetSymbolAddress((void**)&kp,   g_k);
    cudaGetSymbolAddress((void**)&vtp,  g_vt);
    cudaGetSymbolAddress((void**)&ctxp, g_ctx);

    cudaFuncSetAttribute(gemm_tc_kernel,
                         cudaFuncAttributeMaxDynamicSharedMemorySize, GK_SMEM_BYTES);
    cudaFuncSetAttribute(attn_tc_kernel,
                         cudaFuncAttributeMaxDynamicSharedMemorySize, ATT_SMEM_BYTES);

    // 1) QKV projection; epilogue emits q/k [bh][l][d], v transposed [bh][d][l]
    gemm_tc_kernel<<<dim3(3 * D_ / 128, NT_ / 128), 256, GK_SMEM_BYTES>>>(
        x, W_qkv, nullptr, qp, kp, vtp, NT_, 3 * D_, D_, 1);

    // 2) causal flash attention (3xTF32)
    attn_tc_kernel<<<dim3(L_ / 64, BH_), 128, ATT_SMEM_BYTES>>>(qp, kp, vtp, ctxp);

    // 3) output projection
    gemm_tc_kernel<<<dim3(D_ / 128, NT_ / 128), 256, GK_SMEM_BYTES>>>(
        ctxp, W_out, out, nullptr, nullptr, nullptr, NT_, D_, D_, 0);
}